// round 8
// baseline (speedup 1.0000x reference)
#include <cuda_runtime.h>
#include <cuda_fp16.h>
#include <cstdint>

#define NIMG 8
#define CDIM 512
#define HDIM 32
#define WDIM 32
#define ODIM 512
#define KW   5
#define HH   28
#define WWN  28
#define NWIN (NIMG*HH*WWN)      // 6272
#define NPIX (NIMG*HDIM*WDIM)   // 8192
#define PIX_PER_IMG (HH*WWN)    // 784
#define LNEPS 1e-5f

// ---------------- scratch (no allocations allowed) ----------------
__device__ float g_score[NPIX];
__device__ __half g_xh[(size_t)NPIX * CDIM];     // 8.4MB fp16 copy of x
__device__ __half g_xa_h[(size_t)NWIN * CDIM];   // 6.4MB
__device__ __half g_pw_h[ODIM * CDIM];

__device__ __forceinline__ uint32_t s2u(const void* p) {
    return (uint32_t)__cvta_generic_to_shared(p);
}
__device__ __forceinline__ void ldmx4(uint32_t r[4], uint32_t a) {
    asm volatile("ldmatrix.sync.aligned.m8n8.x4.shared.b16 {%0,%1,%2,%3}, [%4];"
        : "=r"(r[0]), "=r"(r[1]), "=r"(r[2]), "=r"(r[3]) : "r"(a));
}
__device__ __forceinline__ void mma16816(float d[4], const uint32_t a[4], const uint32_t b[2]) {
    asm volatile("mma.sync.aligned.m16n8k16.row.col.f32.f16.f16.f32 "
        "{%0,%1,%2,%3}, {%4,%5,%6,%7}, {%8,%9}, {%0,%1,%2,%3};"
        : "+f"(d[0]), "+f"(d[1]), "+f"(d[2]), "+f"(d[3])
        : "r"(a[0]), "r"(a[1]), "r"(a[2]), "r"(a[3]), "r"(b[0]), "r"(b[1]));
}
__device__ __forceinline__ void cpasync16(uint32_t s, const void* g) {
    asm volatile("cp.async.cg.shared.global [%0], [%1], 16;" :: "r"(s), "l"(g));
}
#define CP_COMMIT() asm volatile("cp.async.commit_group;" ::: "memory")
#define CP_WAIT1()  asm volatile("cp.async.wait_group 1;" ::: "memory")

__device__ __forceinline__ uint2 pack4h(float4 v) {
    __half2 a; a.x = __float2half(v.x); a.y = __float2half(v.y);
    __half2 b; b.x = __float2half(v.z); b.y = __float2half(v.w);
    uint2 r;
    r.x = *(uint32_t*)&a;
    r.y = *(uint32_t*)&b;
    return r;
}

// ---------------------------------------------------------------------------
// K1 (fused, first kernel - absorbs launch ramp):
//   blocks [0,256): score GEMV (4 pixels/warp) + write fp16 copy of x
//   blocks [256,1280): proj_w fp16 cast
// ---------------------------------------------------------------------------
__global__ void score_prep_kernel(const float* __restrict__ x,
                                  const float* __restrict__ sw,
                                  const float* __restrict__ sb,
                                  const float* __restrict__ pw) {
    if (blockIdx.x >= 256) {
        int i = (blockIdx.x - 256) * 256 + threadIdx.x;   // < 262144
        g_pw_h[i] = __float2half(pw[i]);
        return;
    }
    int gw   = blockIdx.x * 8 + (threadIdx.x >> 5);  // 0..2047
    int lane = threadIdx.x & 31;
    int p0 = gw * 4;
    const float4* xb = (const float4*)(x + (size_t)p0 * CDIM);
    uint2* xh = (uint2*)(g_xh + (size_t)p0 * CDIM);   // 8B per float4
    const float4* w4 = (const float4*)sw;
    float a0 = 0.f, a1 = 0.f, a2 = 0.f, a3 = 0.f;
#pragma unroll
    for (int i = 0; i < 4; i++) {
        float4 vw = __ldg(w4 + lane + 32*i);
        float4 v0 = __ldg(xb + lane + 32*i);
        float4 v1 = __ldg(xb + lane + 32*i + 128);
        float4 v2 = __ldg(xb + lane + 32*i + 256);
        float4 v3 = __ldg(xb + lane + 32*i + 384);
        a0 += v0.x*vw.x + v0.y*vw.y + v0.z*vw.z + v0.w*vw.w;
        a1 += v1.x*vw.x + v1.y*vw.y + v1.z*vw.z + v1.w*vw.w;
        a2 += v2.x*vw.x + v2.y*vw.y + v2.z*vw.z + v2.w*vw.w;
        a3 += v3.x*vw.x + v3.y*vw.y + v3.z*vw.z + v3.w*vw.w;
        xh[lane + 32*i]       = pack4h(v0);
        xh[lane + 32*i + 128] = pack4h(v1);
        xh[lane + 32*i + 256] = pack4h(v2);
        xh[lane + 32*i + 384] = pack4h(v3);
    }
#pragma unroll
    for (int o = 16; o; o >>= 1) {
        a0 += __shfl_xor_sync(0xffffffffu, a0, o);
        a1 += __shfl_xor_sync(0xffffffffu, a1, o);
        a2 += __shfl_xor_sync(0xffffffffu, a2, o);
        a3 += __shfl_xor_sync(0xffffffffu, a3, o);
    }
    if (lane == 0) {
        float b = sb[0];
        g_score[p0]   = a0 + b;
        g_score[p0+1] = a1 + b;
        g_score[p0+2] = a2 + b;
        g_score[p0+3] = a3 + b;
    }
}

// ---------------------------------------------------------------------------
// K2: 4x4 windows per block (one 8x8 pixel patch), 392 blocks x 256 threads,
//     2 channels/thread. Reads fp16 x copy, fp32 accumulation, fp16 out.
// ---------------------------------------------------------------------------
__global__ __launch_bounds__(256)
void attn_agg_kernel(const float* __restrict__ lnw,
                     const float* __restrict__ lnb) {
    const int b  = blockIdx.x;           // NIMG*7*7 = 392
    const int n  = b / 49;
    const int rb = b % 49;
    const int hh0 = (rb / 7) * 4;        // 0..24
    const int ww0 = (rb % 7) * 4;        // 0..24
    const int t = threadIdx.x;

    __shared__ float sfin[64];
    __shared__ float wgt[16][25];
    if (t < 64) {
        int ki = t >> 3, kj = t & 7;
        sfin[t] = g_score[(n*HDIM + hh0 + ki)*WDIM + ww0 + kj];
    }
    __syncthreads();
    if (t < 16) {
        int wr = t >> 2, wc = t & 3;
        float sc[25];
#pragma unroll
        for (int a = 0; a < 5; a++)
#pragma unroll
            for (int c = 0; c < 5; c++) sc[a*5+c] = sfin[(wr+a)*8 + wc + c];
        float mu = 0.f;
#pragma unroll
        for (int k = 0; k < 25; k++) mu += sc[k];
        mu *= (1.f/25.f);
        float var = 0.f;
#pragma unroll
        for (int k = 0; k < 25; k++) { float d = sc[k]-mu; var += d*d; }
        var *= (1.f/25.f);
        float inv = rsqrtf(var + LNEPS);
        float e[25], mx = -1e30f;
#pragma unroll
        for (int k = 0; k < 25; k++) {
            float z = (sc[k]-mu)*inv*lnw[k] + lnb[k];
            e[k] = z; mx = fmaxf(mx, z);
        }
        float sum = 0.f;
#pragma unroll
        for (int k = 0; k < 25; k++) { e[k] = __expf(e[k]-mx); sum += e[k]; }
        float rs = 1.f/sum;
#pragma unroll
        for (int k = 0; k < 25; k++) wgt[t][k] = e[k]*rs;
    }
    __syncthreads();

    float2 acc[4][4];
#pragma unroll
    for (int wr = 0; wr < 4; wr++)
#pragma unroll
        for (int wc = 0; wc < 4; wc++) acc[wr][wc] = make_float2(0.f, 0.f);

    const __half2* xh2 = (const __half2*)g_xh;
#pragma unroll
    for (int ki = 0; ki < 8; ki++) {
        const __half2* rp = xh2 +
            ((size_t)((n*HDIM + hh0 + ki)*WDIM + ww0)) * (CDIM/2) + t;
#pragma unroll
        for (int kj = 0; kj < 8; kj++) {
            float2 v = __half22float2(__ldg(rp + kj*(CDIM/2)));
#pragma unroll
            for (int wr = 0; wr < 4; wr++) {
                if (ki - wr < 0 || ki - wr > 4) continue;
#pragma unroll
                for (int wc = 0; wc < 4; wc++) {
                    if (kj - wc < 0 || kj - wc > 4) continue;
                    float wk = wgt[wr*4 + wc][(ki-wr)*5 + (kj-wc)];
                    acc[wr][wc].x += wk*v.x;
                    acc[wr][wc].y += wk*v.y;
                }
            }
        }
    }

#pragma unroll
    for (int wr = 0; wr < 4; wr++)
#pragma unroll
        for (int wc = 0; wc < 4; wc++) {
            int win = (n*HH + hh0 + wr)*WWN + ww0 + wc;
            __half2 h;
            h.x = __float2half(acc[wr][wc].x);
            h.y = __float2half(acc[wr][wc].y);
            *((__half2*)(g_xa_h + (size_t)win*CDIM) + t) = h;
        }
}

// ---------------------------------------------------------------------------
// K3: plain fp16 HMMA GEMM. CTA 128x64, KCH=64, SW128 swizzle, 3-stage
//     cp.async, 8 warps (32x32 warp tile), 3 CTAs/SM -> single wave.
// ---------------------------------------------------------------------------
#define BM 128
#define BN 64
#define KCH 64
#define NCH (CDIM/KCH)            // 8
#define ATILE_B (BM*128)          // 16384
#define BTILE_B (BN*128)          // 8192
#define STAGE_B (ATILE_B + BTILE_B)   // 24576
#define NSTG 3
#define DSMEM_B (NSTG*STAGE_B)    // 73728 >= epi 33280

__global__ __launch_bounds__(256, 3)
void hmma_gemm_kernel(const float* __restrict__ pb, float* __restrict__ out) {
    extern __shared__ char dsm[];
    const int tid = threadIdx.x, wid = tid >> 5, lane = tid & 31;
    const int bm = blockIdx.x * BM, bn = blockIdx.y * BN;
    const int m_org = (wid & 3) * 32;
    const int n_org = (wid >> 2) * 32;
    const int quad = lane >> 3, rq = lane & 7;

    float acc[2][4][4];
#pragma unroll
    for (int a = 0; a < 2; a++)
#pragma unroll
        for (int b = 0; b < 4; b++)
#pragma unroll
            for (int c = 0; c < 4; c++) acc[a][b][c] = 0.f;

    auto ISSUE = [&](int ck) {
        if (ck < NCH) {
            const int k0 = ck * KCH;
            char* buf = dsm + (ck % NSTG) * STAGE_B;
#pragma unroll
            for (int i = 0; i < 6; i++) {
                int idx = tid + i*256;             // 0..1535
                if (idx < 1024) {
                    int r = idx >> 3, j = idx & 7;
                    uint32_t off = (uint32_t)(r*128 + j*16);
                    off ^= (off >> 3) & 0x70;
                    cpasync16(s2u(buf + off),
                              g_xa_h + (size_t)(bm + r)*CDIM + k0 + j*8);
                } else {
                    int c = idx - 1024, r = c >> 3, j = c & 7;
                    uint32_t off = (uint32_t)(r*128 + j*16);
                    off ^= (off >> 3) & 0x70;
                    cpasync16(s2u(buf + ATILE_B + off),
                              g_pw_h + (size_t)(bn + r)*CDIM + k0 + j*8);
                }
            }
        }
        CP_COMMIT();
    };

    ISSUE(0);
    ISSUE(1);
    for (int ck = 0; ck < NCH; ck++) {
        char* buf = dsm + (ck % NSTG) * STAGE_B;
        CP_WAIT1();
        __syncthreads();
        ISSUE(ck + 2);

        const uint32_t abase = s2u(buf);
        const uint32_t bbase = s2u(buf + ATILE_B);
#pragma unroll
        for (int ks = 0; ks < 4; ks++) {
            const int jA = ks * 2;
            uint32_t ah[2][4];
#pragma unroll
            for (int mi = 0; mi < 2; mi++) {
                int row = m_org + mi*16 + rq + ((quad & 1) << 3);
                int jh = jA + (quad >> 1);
                uint32_t o = (uint32_t)(row*128 + jh*16); o ^= (o >> 3) & 0x70;
                ldmx4(ah[mi], abase + o);
            }
            uint32_t bh[2][4];
#pragma unroll
            for (int nb = 0; nb < 2; nb++) {
                int row = n_org + nb*16 + rq + ((quad >> 1) << 3);
                int jh = jA + (quad & 1);
                uint32_t o = (uint32_t)(row*128 + jh*16); o ^= (o >> 3) & 0x70;
                ldmx4(bh[nb], bbase + o);
            }
#pragma unroll
            for (int mi = 0; mi < 2; mi++)
#pragma unroll
                for (int nj = 0; nj < 4; nj++)
                    mma16816(acc[mi][nj], ah[mi], &bh[nj >> 1][(nj & 1) * 2]);
        }
        __syncthreads();
    }

    // epilogue: transpose through smem for coalesced (o-major) global stores
    float* cs = (float*)dsm;
#pragma unroll
    for (int mi = 0; mi < 2; mi++)
#pragma unroll
        for (int nj = 0; nj < 4; nj++) {
            int row = m_org + mi*16 + (lane >> 2);
            int col = n_org + nj*8 + 2*(lane & 3);
            cs[row*65 + col]       = acc[mi][nj][0];
            cs[row*65 + col + 1]   = acc[mi][nj][1];
            cs[(row+8)*65 + col]   = acc[mi][nj][2];
            cs[(row+8)*65 + col+1] = acc[mi][nj][3];
        }
    __syncthreads();
#pragma unroll 4
    for (int it = 0; it < 32; it++) {
        int linear = it*256 + tid;
        int col = linear >> 7, row = linear & 127;
        int m = bm + row, o = bn + col;
        int nimg = m / PIX_PER_IMG;
        int rem  = m - nimg * PIX_PER_IMG;
        out[(size_t)nimg*ODIM*PIX_PER_IMG + (size_t)o*PIX_PER_IMG + rem] =
            cs[row*65 + col] + __ldg(pb + o);
    }
}

// ---------------------------------------------------------------------------
extern "C" void kernel_launch(void* const* d_in, const int* in_sizes, int n_in,
                              void* d_out, int out_size) {
    const float* x   = (const float*)d_in[0];
    const float* pw  = (const float*)d_in[1];
    const float* pb  = (const float*)d_in[2];
    const float* sw  = (const float*)d_in[3];
    const float* sb  = (const float*)d_in[4];
    const float* lnw = (const float*)d_in[5];
    const float* lnb = (const float*)d_in[6];
    float* out = (float*)d_out;

    cudaFuncSetAttribute(hmma_gemm_kernel,
                         cudaFuncAttributeMaxDynamicSharedMemorySize, DSMEM_B);

    score_prep_kernel<<<1280, 256>>>(x, sw, sb, pw);
    attn_agg_kernel<<<NIMG*7*7, 256>>>(lnw, lnb);
    dim3 grid(NWIN/BM /*49*/, ODIM/BN /*8*/);
    hmma_gemm_kernel<<<grid, 256, DSMEM_B>>>(pb, out);
}

// round 10
// speedup vs baseline: 1.0738x; 1.0738x over previous
#include <cuda_runtime.h>
#include <cuda_fp16.h>
#include <cstdint>

#define NIMG 8
#define CDIM 512
#define HDIM 32
#define WDIM 32
#define ODIM 512
#define KW   5
#define HH   28
#define WWN  28
#define NWIN (NIMG*HH*WWN)      // 6272
#define NPIX (NIMG*HDIM*WDIM)   // 8192
#define PIX_PER_IMG (HH*WWN)    // 784
#define LNEPS 1e-5f

// ---------------- scratch (no allocations allowed) ----------------
__device__ float g_score[NPIX];
__device__ __half g_xa_h[(size_t)NWIN * CDIM];   // 6.4MB
__device__ __half g_pw_h[ODIM * CDIM];

__device__ __forceinline__ uint32_t s2u(const void* p) {
    return (uint32_t)__cvta_generic_to_shared(p);
}
__device__ __forceinline__ void ldmx4(uint32_t r[4], uint32_t a) {
    asm volatile("ldmatrix.sync.aligned.m8n8.x4.shared.b16 {%0,%1,%2,%3}, [%4];"
        : "=r"(r[0]), "=r"(r[1]), "=r"(r[2]), "=r"(r[3]) : "r"(a));
}
__device__ __forceinline__ void mma16816(float d[4], const uint32_t a[4], const uint32_t b[2]) {
    asm volatile("mma.sync.aligned.m16n8k16.row.col.f32.f16.f16.f32 "
        "{%0,%1,%2,%3}, {%4,%5,%6,%7}, {%8,%9}, {%0,%1,%2,%3};"
        : "+f"(d[0]), "+f"(d[1]), "+f"(d[2]), "+f"(d[3])
        : "r"(a[0]), "r"(a[1]), "r"(a[2]), "r"(a[3]), "r"(b[0]), "r"(b[1]));
}
__device__ __forceinline__ void cpasync16(uint32_t s, const void* g) {
    asm volatile("cp.async.cg.shared.global [%0], [%1], 16;" :: "r"(s), "l"(g));
}
#define CP_COMMIT() asm volatile("cp.async.commit_group;" ::: "memory")
#define CP_WAIT1()  asm volatile("cp.async.wait_group 1;" ::: "memory")

// ---------------------------------------------------------------------------
// K1 (fused): blocks [0,256): score GEMV, 4 pixels per warp;
//             blocks [256,512): proj_w fp16 cast (float4 vectorized)
// ---------------------------------------------------------------------------
__global__ void score_prep_kernel(const float* __restrict__ x,
                                  const float* __restrict__ sw,
                                  const float* __restrict__ sb,
                                  const float* __restrict__ pw) {
    if (blockIdx.x >= 256) {
        int i = ((blockIdx.x - 256) * 256 + threadIdx.x) * 4;   // covers 262144
        float4 v = *(const float4*)(pw + i);
        __half2 a; a.x = __float2half(v.x); a.y = __float2half(v.y);
        __half2 b; b.x = __float2half(v.z); b.y = __float2half(v.w);
        *(__half2*)(g_pw_h + i)     = a;
        *(__half2*)(g_pw_h + i + 2) = b;
        return;
    }
    int gw   = blockIdx.x * 8 + (threadIdx.x >> 5);  // 0..2047
    int lane = threadIdx.x & 31;
    int p0 = gw * 4;
    const float4* xb = (const float4*)(x + (size_t)p0 * CDIM);
    const float4* w4 = (const float4*)sw;
    float a0 = 0.f, a1 = 0.f, a2 = 0.f, a3 = 0.f;
#pragma unroll
    for (int i = 0; i < 4; i++) {
        float4 vw = __ldg(w4 + lane + 32*i);
        float4 v0 = __ldg(xb + lane + 32*i);
        float4 v1 = __ldg(xb + lane + 32*i + 128);
        float4 v2 = __ldg(xb + lane + 32*i + 256);
        float4 v3 = __ldg(xb + lane + 32*i + 384);
        a0 += v0.x*vw.x + v0.y*vw.y + v0.z*vw.z + v0.w*vw.w;
        a1 += v1.x*vw.x + v1.y*vw.y + v1.z*vw.z + v1.w*vw.w;
        a2 += v2.x*vw.x + v2.y*vw.y + v2.z*vw.z + v2.w*vw.w;
        a3 += v3.x*vw.x + v3.y*vw.y + v3.z*vw.z + v3.w*vw.w;
    }
#pragma unroll
    for (int o = 16; o; o >>= 1) {
        a0 += __shfl_xor_sync(0xffffffffu, a0, o);
        a1 += __shfl_xor_sync(0xffffffffu, a1, o);
        a2 += __shfl_xor_sync(0xffffffffu, a2, o);
        a3 += __shfl_xor_sync(0xffffffffu, a3, o);
    }
    if (lane == 0) {
        float b = sb[0];
        g_score[p0]   = a0 + b;
        g_score[p0+1] = a1 + b;
        g_score[p0+2] = a2 + b;
        g_score[p0+3] = a3 + b;
    }
}

// ---------------------------------------------------------------------------
// K2: 4x7 windows per block (one 8x11 pixel patch), 224 blocks x 256 threads,
//     2 channels/thread. LN+softmax per window, stream 88 rows once,
//     accumulate all 28 windows in fp32, fp16 out.
// ---------------------------------------------------------------------------
__global__ __launch_bounds__(256)
void attn_agg_kernel(const float* __restrict__ x,
                     const float* __restrict__ lnw,
                     const float* __restrict__ lnb) {
    const int b  = blockIdx.x;           // NIMG*7*4 = 224
    const int n  = b / 28;
    const int rb = b % 28;
    const int hh0 = (rb >> 2) * 4;       // 0,4,...,24
    const int ww0 = (rb & 3) * 7;        // 0,7,14,21
    const int t = threadIdx.x;

    __shared__ float s[8][11];
    __shared__ float wgt[28][25];
    if (t < 88) {
        int ki = t / 11, kj = t % 11;
        s[ki][kj] = g_score[(n*HDIM + hh0 + ki)*WDIM + ww0 + kj];
    }
    __syncthreads();
    if (t < 28) {
        int wr = t / 7, wc = t % 7;
        float sc[25];
#pragma unroll
        for (int a = 0; a < 5; a++)
#pragma unroll
            for (int c = 0; c < 5; c++) sc[a*5+c] = s[wr+a][wc+c];
        float mu = 0.f;
#pragma unroll
        for (int k = 0; k < 25; k++) mu += sc[k];
        mu *= (1.f/25.f);
        float var = 0.f;
#pragma unroll
        for (int k = 0; k < 25; k++) { float d = sc[k]-mu; var += d*d; }
        var *= (1.f/25.f);
        float inv = rsqrtf(var + LNEPS);
        float e[25], mx = -1e30f;
#pragma unroll
        for (int k = 0; k < 25; k++) {
            float z = (sc[k]-mu)*inv*lnw[k] + lnb[k];
            e[k] = z; mx = fmaxf(mx, z);
        }
        float sum = 0.f;
#pragma unroll
        for (int k = 0; k < 25; k++) { e[k] = __expf(e[k]-mx); sum += e[k]; }
        float rs = 1.f/sum;
#pragma unroll
        for (int k = 0; k < 25; k++) wgt[t][k] = e[k]*rs;
    }
    __syncthreads();

    float2 acc[4][7];
#pragma unroll
    for (int wr = 0; wr < 4; wr++)
#pragma unroll
        for (int wc = 0; wc < 7; wc++) acc[wr][wc] = make_float2(0.f, 0.f);

#pragma unroll
    for (int ki = 0; ki < 8; ki++) {
        const float2* rbp = (const float2*)(x +
            ((size_t)((n*HDIM + hh0 + ki)*WDIM + ww0)) * CDIM) + t;
#pragma unroll
        for (int kj = 0; kj < 11; kj++) {
            float2 v = __ldg(rbp + kj*(CDIM/2));
#pragma unroll
            for (int wr = 0; wr < 4; wr++) {
                if (ki - wr < 0 || ki - wr > 4) continue;
#pragma unroll
                for (int wc = 0; wc < 7; wc++) {
                    if (kj - wc < 0 || kj - wc > 4) continue;
                    float wk = wgt[wr*7 + wc][(ki-wr)*5 + (kj-wc)];
                    acc[wr][wc].x += wk*v.x;
                    acc[wr][wc].y += wk*v.y;
                }
            }
        }
    }

#pragma unroll
    for (int wr = 0; wr < 4; wr++)
#pragma unroll
        for (int wc = 0; wc < 7; wc++) {
            int win = (n*HH + hh0 + wr)*WWN + ww0 + wc;
            __half2 h;
            h.x = __float2half(acc[wr][wc].x);
            h.y = __float2half(acc[wr][wc].y);
            *((__half2*)(g_xa_h + (size_t)win*CDIM) + t) = h;
        }
}

// ---------------------------------------------------------------------------
// K3: plain fp16 HMMA GEMM. CTA 128x64, KCH=64, SW128 swizzle, 3-stage
//     cp.async, 8 warps (32x32 warp tile), 3 CTAs/SM -> single wave.
// ---------------------------------------------------------------------------
#define BM 128
#define BN 64
#define KCH 64
#define NCH (CDIM/KCH)            // 8
#define ATILE_B (BM*128)          // 16384
#define BTILE_B (BN*128)          // 8192
#define STAGE_B (ATILE_B + BTILE_B)   // 24576
#define NSTG 3
#define DSMEM_B (NSTG*STAGE_B)    // 73728 >= epi 33280

__global__ __launch_bounds__(256, 3)
void hmma_gemm_kernel(const float* __restrict__ pb, float* __restrict__ out) {
    extern __shared__ char dsm[];
    const int tid = threadIdx.x, wid = tid >> 5, lane = tid & 31;
    const int bm = blockIdx.x * BM, bn = blockIdx.y * BN;
    const int m_org = (wid & 3) * 32;
    const int n_org = (wid >> 2) * 32;
    const int quad = lane >> 3, rq = lane & 7;

    float acc[2][4][4];
#pragma unroll
    for (int a = 0; a < 2; a++)
#pragma unroll
        for (int b = 0; b < 4; b++)
#pragma unroll
            for (int c = 0; c < 4; c++) acc[a][b][c] = 0.f;

    auto ISSUE = [&](int ck) {
        if (ck < NCH) {
            const int k0 = ck * KCH;
            char* buf = dsm + (ck % NSTG) * STAGE_B;
#pragma unroll
            for (int i = 0; i < 6; i++) {
                int idx = tid + i*256;             // 0..1535
                if (idx < 1024) {
                    int r = idx >> 3, j = idx & 7;
                    uint32_t off = (uint32_t)(r*128 + j*16);
                    off ^= (off >> 3) & 0x70;
                    cpasync16(s2u(buf + off),
                              g_xa_h + (size_t)(bm + r)*CDIM + k0 + j*8);
                } else {
                    int c = idx - 1024, r = c >> 3, j = c & 7;
                    uint32_t off = (uint32_t)(r*128 + j*16);
                    off ^= (off >> 3) & 0x70;
                    cpasync16(s2u(buf + ATILE_B + off),
                              g_pw_h + (size_t)(bn + r)*CDIM + k0 + j*8);
                }
            }
        }
        CP_COMMIT();
    };

    ISSUE(0);
    ISSUE(1);
    for (int ck = 0; ck < NCH; ck++) {
        char* buf = dsm + (ck % NSTG) * STAGE_B;
        CP_WAIT1();
        __syncthreads();
        ISSUE(ck + 2);

        const uint32_t abase = s2u(buf);
        const uint32_t bbase = s2u(buf + ATILE_B);
#pragma unroll
        for (int ks = 0; ks < 4; ks++) {
            const int jA = ks * 2;
            uint32_t ah[2][4];
#pragma unroll
            for (int mi = 0; mi < 2; mi++) {
                int row = m_org + mi*16 + rq + ((quad & 1) << 3);
                int jh = jA + (quad >> 1);
                uint32_t o = (uint32_t)(row*128 + jh*16); o ^= (o >> 3) & 0x70;
                ldmx4(ah[mi], abase + o);
            }
            uint32_t bh[2][4];
#pragma unroll
            for (int nb = 0; nb < 2; nb++) {
                int row = n_org + nb*16 + rq + ((quad >> 1) << 3);
                int jh = jA + (quad & 1);
                uint32_t o = (uint32_t)(row*128 + jh*16); o ^= (o >> 3) & 0x70;
                ldmx4(bh[nb], bbase + o);
            }
#pragma unroll
            for (int mi = 0; mi < 2; mi++)
#pragma unroll
                for (int nj = 0; nj < 4; nj++)
                    mma16816(acc[mi][nj], ah[mi], &bh[nj >> 1][(nj & 1) * 2]);
        }
        __syncthreads();
    }

    // epilogue: transpose through smem for coalesced (o-major) global stores
    float* cs = (float*)dsm;
#pragma unroll
    for (int mi = 0; mi < 2; mi++)
#pragma unroll
        for (int nj = 0; nj < 4; nj++) {
            int row = m_org + mi*16 + (lane >> 2);
            int col = n_org + nj*8 + 2*(lane & 3);
            cs[row*65 + col]       = acc[mi][nj][0];
            cs[row*65 + col + 1]   = acc[mi][nj][1];
            cs[(row+8)*65 + col]   = acc[mi][nj][2];
            cs[(row+8)*65 + col+1] = acc[mi][nj][3];
        }
    __syncthreads();
#pragma unroll 4
    for (int it = 0; it < 32; it++) {
        int linear = it*256 + tid;
        int col = linear >> 7, row = linear & 127;
        int m = bm + row, o = bn + col;
        int nimg = m / PIX_PER_IMG;
        int rem  = m - nimg * PIX_PER_IMG;
        out[(size_t)nimg*ODIM*PIX_PER_IMG + (size_t)o*PIX_PER_IMG + rem] =
            cs[row*65 + col] + __ldg(pb + o);
    }
}

// ---------------------------------------------------------------------------
extern "C" void kernel_launch(void* const* d_in, const int* in_sizes, int n_in,
                              void* d_out, int out_size) {
    const float* x   = (const float*)d_in[0];
    const float* pw  = (const float*)d_in[1];
    const float* pb  = (const float*)d_in[2];
    const float* sw  = (const float*)d_in[3];
    const float* sb  = (const float*)d_in[4];
    const float* lnw = (const float*)d_in[5];
    const float* lnb = (const float*)d_in[6];
    float* out = (float*)d_out;

    cudaFuncSetAttribute(hmma_gemm_kernel,
                         cudaFuncAttributeMaxDynamicSharedMemorySize, DSMEM_B);

    score_prep_kernel<<<512, 256>>>(x, sw, sb, pw);
    attn_agg_kernel<<<NIMG*7*4, 256>>>(x, lnw, lnb);
    dim3 grid(NWIN/BM /*49*/, ODIM/BN /*8*/);
    hmma_gemm_kernel<<<grid, 256, DSMEM_B>>>(pb, out);
}

// round 11
// speedup vs baseline: 1.1504x; 1.0714x over previous
#include <cuda_runtime.h>
#include <cuda_fp16.h>
#include <cstdint>

#define NIMG 8
#define CDIM 512
#define HDIM 32
#define WDIM 32
#define ODIM 512
#define KW   5
#define HH   28
#define WWN  28
#define NWIN (NIMG*HH*WWN)      // 6272
#define NPIX (NIMG*HDIM*WDIM)   // 8192
#define PIX_PER_IMG (HH*WWN)    // 784
#define LNEPS 1e-5f

// ---------------- scratch (no allocations allowed) ----------------
__device__ float g_score[NPIX];
__device__ __half g_xa_h[(size_t)NWIN * CDIM];   // 6.4MB
__device__ __half g_pw_h[ODIM * CDIM];

__device__ __forceinline__ uint32_t s2u(const void* p) {
    return (uint32_t)__cvta_generic_to_shared(p);
}
__device__ __forceinline__ void ldmx4(uint32_t r[4], uint32_t a) {
    asm volatile("ldmatrix.sync.aligned.m8n8.x4.shared.b16 {%0,%1,%2,%3}, [%4];"
        : "=r"(r[0]), "=r"(r[1]), "=r"(r[2]), "=r"(r[3]) : "r"(a));
}
__device__ __forceinline__ void mma16816(float d[4], const uint32_t a[4], const uint32_t b[2]) {
    asm volatile("mma.sync.aligned.m16n8k16.row.col.f32.f16.f16.f32 "
        "{%0,%1,%2,%3}, {%4,%5,%6,%7}, {%8,%9}, {%0,%1,%2,%3};"
        : "+f"(d[0]), "+f"(d[1]), "+f"(d[2]), "+f"(d[3])
        : "r"(a[0]), "r"(a[1]), "r"(a[2]), "r"(a[3]), "r"(b[0]), "r"(b[1]));
}
__device__ __forceinline__ void cpasync16(uint32_t s, const void* g) {
    asm volatile("cp.async.cg.shared.global [%0], [%1], 16;" :: "r"(s), "l"(g));
}
#define CP_COMMIT() asm volatile("cp.async.commit_group;" ::: "memory")
#define CP_WAIT1()  asm volatile("cp.async.wait_group 1;" ::: "memory")

// ---------------------------------------------------------------------------
// K1 (fused): blocks [0,256): score GEMV, 4 pixels per warp;
//             blocks [256,512): proj_w fp16 cast (float4 vectorized)
// ---------------------------------------------------------------------------
__global__ void score_prep_kernel(const float* __restrict__ x,
                                  const float* __restrict__ sw,
                                  const float* __restrict__ sb,
                                  const float* __restrict__ pw) {
    if (blockIdx.x >= 256) {
        int i = ((blockIdx.x - 256) * 256 + threadIdx.x) * 4;   // covers 262144
        float4 v = *(const float4*)(pw + i);
        __half2 a; a.x = __float2half(v.x); a.y = __float2half(v.y);
        __half2 b; b.x = __float2half(v.z); b.y = __float2half(v.w);
        *(__half2*)(g_pw_h + i)     = a;
        *(__half2*)(g_pw_h + i + 2) = b;
        return;
    }
    int gw   = blockIdx.x * 8 + (threadIdx.x >> 5);  // 0..2047
    int lane = threadIdx.x & 31;
    int p0 = gw * 4;
    const float4* xb = (const float4*)(x + (size_t)p0 * CDIM);
    const float4* w4 = (const float4*)sw;
    float a0 = 0.f, a1 = 0.f, a2 = 0.f, a3 = 0.f;
#pragma unroll
    for (int i = 0; i < 4; i++) {
        float4 vw = __ldg(w4 + lane + 32*i);
        float4 v0 = __ldg(xb + lane + 32*i);
        float4 v1 = __ldg(xb + lane + 32*i + 128);
        float4 v2 = __ldg(xb + lane + 32*i + 256);
        float4 v3 = __ldg(xb + lane + 32*i + 384);
        a0 += v0.x*vw.x + v0.y*vw.y + v0.z*vw.z + v0.w*vw.w;
        a1 += v1.x*vw.x + v1.y*vw.y + v1.z*vw.z + v1.w*vw.w;
        a2 += v2.x*vw.x + v2.y*vw.y + v2.z*vw.z + v2.w*vw.w;
        a3 += v3.x*vw.x + v3.y*vw.y + v3.z*vw.z + v3.w*vw.w;
    }
#pragma unroll
    for (int o = 16; o; o >>= 1) {
        a0 += __shfl_xor_sync(0xffffffffu, a0, o);
        a1 += __shfl_xor_sync(0xffffffffu, a1, o);
        a2 += __shfl_xor_sync(0xffffffffu, a2, o);
        a3 += __shfl_xor_sync(0xffffffffu, a3, o);
    }
    if (lane == 0) {
        float b = sb[0];
        g_score[p0]   = a0 + b;
        g_score[p0+1] = a1 + b;
        g_score[p0+2] = a2 + b;
        g_score[p0+3] = a3 + b;
    }
}

// ---------------------------------------------------------------------------
// K2: 4x7 windows per block, channel-split x2: 448 blocks x 64 threads,
//     each block does one 8x11 patch for 256 of the 512 channels,
//     float4 per thread. LN+softmax per window (recomputed per half),
//     fp32 accumulation, fp16 out.
// ---------------------------------------------------------------------------
__global__ __launch_bounds__(64)
void attn_agg_kernel(const float* __restrict__ x,
                     const float* __restrict__ lnw,
                     const float* __restrict__ lnb) {
    const int b   = blockIdx.x;          // 448
    const int half = b & 1;
    const int pb2  = b >> 1;             // 0..223
    const int n  = pb2 / 28;
    const int rb = pb2 % 28;
    const int hh0 = (rb >> 2) * 4;       // 0,4,...,24
    const int ww0 = (rb & 3) * 7;        // 0,7,14,21
    const int coff = half * 256;
    const int t = threadIdx.x;           // 0..63

    __shared__ float s[8][11];
    __shared__ float wgt[28][25];
    for (int idx = t; idx < 88; idx += 64) {
        int ki = idx / 11, kj = idx % 11;
        s[ki][kj] = g_score[(n*HDIM + hh0 + ki)*WDIM + ww0 + kj];
    }
    __syncthreads();
    if (t < 28) {
        int wr = t / 7, wc = t % 7;
        float sc[25];
#pragma unroll
        for (int a = 0; a < 5; a++)
#pragma unroll
            for (int c = 0; c < 5; c++) sc[a*5+c] = s[wr+a][wc+c];
        float mu = 0.f;
#pragma unroll
        for (int k = 0; k < 25; k++) mu += sc[k];
        mu *= (1.f/25.f);
        float var = 0.f;
#pragma unroll
        for (int k = 0; k < 25; k++) { float d = sc[k]-mu; var += d*d; }
        var *= (1.f/25.f);
        float inv = rsqrtf(var + LNEPS);
        float e[25], mx = -1e30f;
#pragma unroll
        for (int k = 0; k < 25; k++) {
            float z = (sc[k]-mu)*inv*lnw[k] + lnb[k];
            e[k] = z; mx = fmaxf(mx, z);
        }
        float sum = 0.f;
#pragma unroll
        for (int k = 0; k < 25; k++) { e[k] = __expf(e[k]-mx); sum += e[k]; }
        float rs = 1.f/sum;
#pragma unroll
        for (int k = 0; k < 25; k++) wgt[t][k] = e[k]*rs;
    }
    __syncthreads();

    float4 acc[4][7];
#pragma unroll
    for (int wr = 0; wr < 4; wr++)
#pragma unroll
        for (int wc = 0; wc < 7; wc++) acc[wr][wc] = make_float4(0.f,0.f,0.f,0.f);

#pragma unroll
    for (int ki = 0; ki < 8; ki++) {
        const float4* rbp = (const float4*)(x +
            ((size_t)((n*HDIM + hh0 + ki)*WDIM + ww0)) * CDIM + coff) + t;
#pragma unroll
        for (int kj = 0; kj < 11; kj++) {
            float4 v = __ldg(rbp + kj*(CDIM/4));
#pragma unroll
            for (int wr = 0; wr < 4; wr++) {
                if (ki - wr < 0 || ki - wr > 4) continue;
#pragma unroll
                for (int wc = 0; wc < 7; wc++) {
                    if (kj - wc < 0 || kj - wc > 4) continue;
                    float wk = wgt[wr*7 + wc][(ki-wr)*5 + (kj-wc)];
                    acc[wr][wc].x += wk*v.x; acc[wr][wc].y += wk*v.y;
                    acc[wr][wc].z += wk*v.z; acc[wr][wc].w += wk*v.w;
                }
            }
        }
    }

#pragma unroll
    for (int wr = 0; wr < 4; wr++)
#pragma unroll
        for (int wc = 0; wc < 7; wc++) {
            int win = (n*HH + hh0 + wr)*WWN + ww0 + wc;
            size_t base = (size_t)win*CDIM + coff + t*4;
            __half2 H0; H0.x = __float2half(acc[wr][wc].x); H0.y = __float2half(acc[wr][wc].y);
            __half2 H1; H1.x = __float2half(acc[wr][wc].z); H1.y = __float2half(acc[wr][wc].w);
            *(__half2*)(g_xa_h + base)     = H0;
            *(__half2*)(g_xa_h + base + 2) = H1;
        }
}

// ---------------------------------------------------------------------------
// K3: plain fp16 HMMA GEMM. CTA 128x64, KCH=64, SW128 swizzle, 3-stage
//     cp.async, 8 warps (32x32 warp tile), 3 CTAs/SM -> single wave.
// ---------------------------------------------------------------------------
#define BM 128
#define BN 64
#define KCH 64
#define NCH (CDIM/KCH)            // 8
#define ATILE_B (BM*128)          // 16384
#define BTILE_B (BN*128)          // 8192
#define STAGE_B (ATILE_B + BTILE_B)   // 24576
#define NSTG 3
#define DSMEM_B (NSTG*STAGE_B)    // 73728 >= epi 33280

__global__ __launch_bounds__(256, 3)
void hmma_gemm_kernel(const float* __restrict__ pb, float* __restrict__ out) {
    extern __shared__ char dsm[];
    const int tid = threadIdx.x, wid = tid >> 5, lane = tid & 31;
    const int bm = blockIdx.x * BM, bn = blockIdx.y * BN;
    const int m_org = (wid & 3) * 32;
    const int n_org = (wid >> 2) * 32;
    const int quad = lane >> 3, rq = lane & 7;

    float acc[2][4][4];
#pragma unroll
    for (int a = 0; a < 2; a++)
#pragma unroll
        for (int b = 0; b < 4; b++)
#pragma unroll
            for (int c = 0; c < 4; c++) acc[a][b][c] = 0.f;

    auto ISSUE = [&](int ck) {
        if (ck < NCH) {
            const int k0 = ck * KCH;
            char* buf = dsm + (ck % NSTG) * STAGE_B;
#pragma unroll
            for (int i = 0; i < 6; i++) {
                int idx = tid + i*256;             // 0..1535
                if (idx < 1024) {
                    int r = idx >> 3, j = idx & 7;
                    uint32_t off = (uint32_t)(r*128 + j*16);
                    off ^= (off >> 3) & 0x70;
                    cpasync16(s2u(buf + off),
                              g_xa_h + (size_t)(bm + r)*CDIM + k0 + j*8);
                } else {
                    int c = idx - 1024, r = c >> 3, j = c & 7;
                    uint32_t off = (uint32_t)(r*128 + j*16);
                    off ^= (off >> 3) & 0x70;
                    cpasync16(s2u(buf + ATILE_B + off),
                              g_pw_h + (size_t)(bn + r)*CDIM + k0 + j*8);
                }
            }
        }
        CP_COMMIT();
    };

    ISSUE(0);
    ISSUE(1);
    for (int ck = 0; ck < NCH; ck++) {
        char* buf = dsm + (ck % NSTG) * STAGE_B;
        CP_WAIT1();
        __syncthreads();
        ISSUE(ck + 2);

        const uint32_t abase = s2u(buf);
        const uint32_t bbase = s2u(buf + ATILE_B);
#pragma unroll
        for (int ks = 0; ks < 4; ks++) {
            const int jA = ks * 2;
            uint32_t ah[2][4];
#pragma unroll
            for (int mi = 0; mi < 2; mi++) {
                int row = m_org + mi*16 + rq + ((quad & 1) << 3);
                int jh = jA + (quad >> 1);
                uint32_t o = (uint32_t)(row*128 + jh*16); o ^= (o >> 3) & 0x70;
                ldmx4(ah[mi], abase + o);
            }
            uint32_t bh[2][4];
#pragma unroll
            for (int nb = 0; nb < 2; nb++) {
                int row = n_org + nb*16 + rq + ((quad >> 1) << 3);
                int jh = jA + (quad & 1);
                uint32_t o = (uint32_t)(row*128 + jh*16); o ^= (o >> 3) & 0x70;
                ldmx4(bh[nb], bbase + o);
            }
#pragma unroll
            for (int mi = 0; mi < 2; mi++)
#pragma unroll
                for (int nj = 0; nj < 4; nj++)
                    mma16816(acc[mi][nj], ah[mi], &bh[nj >> 1][(nj & 1) * 2]);
        }
        __syncthreads();
    }

    // epilogue: transpose through smem for coalesced (o-major) global stores
    float* cs = (float*)dsm;
#pragma unroll
    for (int mi = 0; mi < 2; mi++)
#pragma unroll
        for (int nj = 0; nj < 4; nj++) {
            int row = m_org + mi*16 + (lane >> 2);
            int col = n_org + nj*8 + 2*(lane & 3);
            cs[row*65 + col]       = acc[mi][nj][0];
            cs[row*65 + col + 1]   = acc[mi][nj][1];
            cs[(row+8)*65 + col]   = acc[mi][nj][2];
            cs[(row+8)*65 + col+1] = acc[mi][nj][3];
        }
    __syncthreads();
#pragma unroll 4
    for (int it = 0; it < 32; it++) {
        int linear = it*256 + tid;
        int col = linear >> 7, row = linear & 127;
        int m = bm + row, o = bn + col;
        int nimg = m / PIX_PER_IMG;
        int rem  = m - nimg * PIX_PER_IMG;
        out[(size_t)nimg*ODIM*PIX_PER_IMG + (size_t)o*PIX_PER_IMG + rem] =
            cs[row*65 + col] + __ldg(pb + o);
    }
}

// ---------------------------------------------------------------------------
extern "C" void kernel_launch(void* const* d_in, const int* in_sizes, int n_in,
                              void* d_out, int out_size) {
    const float* x   = (const float*)d_in[0];
    const float* pw  = (const float*)d_in[1];
    const float* pb  = (const float*)d_in[2];
    const float* sw  = (const float*)d_in[3];
    const float* sb  = (const float*)d_in[4];
    const float* lnw = (const float*)d_in[5];
    const float* lnb = (const float*)d_in[6];
    float* out = (float*)d_out;

    cudaFuncSetAttribute(hmma_gemm_kernel,
                         cudaFuncAttributeMaxDynamicSharedMemorySize, DSMEM_B);

    score_prep_kernel<<<512, 256>>>(x, sw, sb, pw);
    attn_agg_kernel<<<448, 64>>>(x, lnw, lnb);
    dim3 grid(NWIN/BM /*49*/, ODIM/BN /*8*/);
    hmma_gemm_kernel<<<grid, 256, DSMEM_B>>>(pb, out);
}